// round 7
// baseline (speedup 1.0000x reference)
#include <cuda_runtime.h>
#include <cuda_fp16.h>
#include <mma.h>
#include <math.h>

using namespace nvcuda;

#define V_NODES 10000
#define DEG 32
#define E_EDGES (V_NODES * DEG)

#define BUFSZ (V_NODES * 2048)
// 6 big buffers + bn stats + pool partials + scratch (fp16 weight splits, bias tiles)
__device__ float g_buf[6 * BUFSZ + 4 * 256 + 25 * 2048 + 1048576];

// ---------------------------------------------------------------------------
// transpose input x (B,8,V) -> fp16 (V, c*16+b)
// ---------------------------------------------------------------------------
__global__ void transpose_x_kernel(__half* __restrict__ out, const float* __restrict__ x) {
    int i = blockIdx.x * 256 + threadIdx.x;
    if (i >= V_NODES * 128) return;
    int b = i & 15;
    int c = (i >> 4) & 7;
    int v = i >> 7;
    out[i] = __float2half(x[(b * 8 + c) * V_NODES + v]);
}

// ---------------------------------------------------------------------------
// weight split: W (fp32) -> Whi + Wlo (fp16 pair, fp32-equivalent precision)
// ---------------------------------------------------------------------------
__global__ void wsplit_kernel(__half* __restrict__ hi, __half* __restrict__ lo,
                              const float* __restrict__ w, int n) {
    int i = blockIdx.x * 256 + threadIdx.x;
    if (i >= n) return;
    float v = w[i];
    __half h = __float2half_rn(v);
    hi[i] = h;
    lo[i] = __float2half_rn(v - __half2float(h));
}

// bias broadcast tile: bt[o*16+b] = bias[o]
__global__ void btile_kernel(float* __restrict__ bt, const float* __restrict__ bias, int cout) {
    int i = blockIdx.x * 256 + threadIdx.x;
    if (i < cout * 16) bt[i] = bias[i >> 4];
}

// ---------------------------------------------------------------------------
// SPMM role body (shared): Tnew = L @ Tp1 (FIRST) | 2 L @ Tp1 - Tp2, fp16 T
// ---------------------------------------------------------------------------
template<int CIN, bool FIRST>
__device__ __forceinline__ void spmm_role(
    int sb, int tid, float* smbuf,
    __half* __restrict__ Tnew, const __half* __restrict__ Tp1, const __half* __restrict__ Tp2,
    const int* __restrict__ col, const float* __restrict__ vals)
{
    constexpr int F8 = CIN * 2;                 // row length in uint4 (8 halves)
    constexpr int TPN = (F8 < 256) ? F8 : 256;
    constexpr int NPB = 256 / TPN;

    int* scol = (int*)smbuf;
    float* sval = smbuf + NPB * DEG;
    int v0 = sb * NPB;
    for (int i = tid; i < NPB * DEG; i += 256) {
        scol[i] = col[v0 * DEG + i];
        sval[i] = vals[v0 * DEG + i];
    }
    __syncthreads();

    int ln = tid / TPN;
    int v = v0 + ln;
    int f0 = tid - ln * TPN;

    const uint4* z4 = (const uint4*)Tp1;
    const uint4* p4 = (const uint4*)Tp2;
    uint4* y4 = (uint4*)Tnew;

    for (int f = f0; f < F8; f += TPN) {
        float acc[8];
#pragma unroll
        for (int i = 0; i < 8; i++) acc[i] = 0.f;
#pragma unroll 8
        for (int e = 0; e < DEG; e++) {
            float w = sval[ln * DEG + e];
            uint4 raw = z4[(size_t)scol[ln * DEG + e] * F8 + f];
            const __half2* h2 = (const __half2*)&raw;
#pragma unroll
            for (int i = 0; i < 4; i++) {
                float2 zz = __half22float2(h2[i]);
                acc[2 * i]     = fmaf(w, zz.x, acc[2 * i]);
                acc[2 * i + 1] = fmaf(w, zz.y, acc[2 * i + 1]);
            }
        }
        if (!FIRST) {
            uint4 raw = p4[(size_t)v * F8 + f];
            const __half2* h2 = (const __half2*)&raw;
#pragma unroll
            for (int i = 0; i < 4; i++) {
                float2 p = __half22float2(h2[i]);
                acc[2 * i]     = 2.f * acc[2 * i]     - p.x;
                acc[2 * i + 1] = 2.f * acc[2 * i + 1] - p.y;
            }
        }
        uint4 o;
        __half2* oh = (__half2*)&o;
#pragma unroll
        for (int i = 0; i < 4; i++)
            oh[i] = __floats2half2_rn(acc[2 * i], acc[2 * i + 1]);
        y4[(size_t)v * F8 + f] = o;
    }
}

// host-side spmm grid helper
static inline int ns_for(int cin) {
    int f8 = cin * 2;
    int tpn = (f8 < 256) ? f8 : 256;
    return V_NODES / (256 / tpn);
}

// ---------------------------------------------------------------------------
// Tensor-core term kernel (CIN multiple of 16).
//   blocks [0, NGEMM):  wmma GEMM role: out tile (+)= T @ (Whi+Wlo) [+ T2 @ W2]
//   blocks [NGEMM, +NS): spmm role
// Per warp: one (node, o-tile) job. A = T tile (b,c) col-major ld16 from gmem.
// B = W chunk (c,o) row-major ldCOUT. C = out tile (b,o) col-major ld16.
// ---------------------------------------------------------------------------
template<int CIN, int COUT, int CIN2, bool FIRST, bool INIT, bool WITH_SPMM>
__global__ void __launch_bounds__(256) term_mma_kernel(
    __half* __restrict__ Tnew, const __half* __restrict__ Tp1, const __half* __restrict__ Tp2,
    float* __restrict__ out,
    const __half* __restrict__ Whi, const __half* __restrict__ Wlo, const float* __restrict__ btile,
    const __half* __restrict__ T2in, const __half* __restrict__ W2hi, const __half* __restrict__ W2lo,
    const int* __restrict__ col, const float* __restrict__ vals)
{
    constexpr int OT = COUT / 16;        // o-tiles per node
    constexpr int NPBG = 8 / OT;         // nodes per gemm block (8 warps)
    constexpr int NGEMM = V_NODES / NPBG;
    constexpr int F8 = CIN * 2;
    constexpr int TPN = (F8 < 256) ? F8 : 256;
    constexpr int NPB = 256 / TPN;
    __shared__ float smbuf[2 * NPB * DEG];

    int tid = threadIdx.x;

    if (blockIdx.x < NGEMM) {
        int w = tid >> 5;
        int v = blockIdx.x * NPBG + w / OT;
        int ot = w % OT;

        wmma::fragment<wmma::accumulator, 16, 16, 16, float> c;
        float* optr = out + (size_t)v * COUT * 16 + ot * 256;
        if (INIT) wmma::load_matrix_sync(c, btile + ot * 256, 16, wmma::mem_col_major);
        else      wmma::load_matrix_sync(c, optr, 16, wmma::mem_col_major);

        const __half* tbase = Tp1 + (size_t)v * CIN * 16;
#pragma unroll
        for (int k = 0; k < CIN / 16; k++) {
            wmma::fragment<wmma::matrix_a, 16, 16, 16, __half, wmma::col_major> a;
            wmma::load_matrix_sync(a, tbase + k * 256, 16);
            wmma::fragment<wmma::matrix_b, 16, 16, 16, __half, wmma::row_major> b;
            wmma::load_matrix_sync(b, Whi + k * 16 * COUT + ot * 16, COUT);
            wmma::mma_sync(c, a, b, c);
            wmma::load_matrix_sync(b, Wlo + k * 16 * COUT + ot * 16, COUT);
            wmma::mma_sync(c, a, b, c);
        }
        if constexpr (CIN2 > 0) {
            const __half* t2 = T2in + (size_t)v * CIN2 * 16;
#pragma unroll
            for (int k = 0; k < CIN2 / 16; k++) {
                wmma::fragment<wmma::matrix_a, 16, 16, 16, __half, wmma::col_major> a;
                wmma::load_matrix_sync(a, t2 + k * 256, 16);
                wmma::fragment<wmma::matrix_b, 16, 16, 16, __half, wmma::row_major> b;
                wmma::load_matrix_sync(b, W2hi + k * 16 * COUT + ot * 16, COUT);
                wmma::mma_sync(c, a, b, c);
                wmma::load_matrix_sync(b, W2lo + k * 16 * COUT + ot * 16, COUT);
                wmma::mma_sync(c, a, b, c);
            }
        }
        wmma::store_matrix_sync(optr, c, 16, wmma::mem_col_major);
    } else if (WITH_SPMM) {
        spmm_role<CIN, FIRST>(blockIdx.x - NGEMM, tid, smbuf, Tnew, Tp1, Tp2, col, vals);
    }
}

// ---------------------------------------------------------------------------
// FFMA term kernel for layer 1 (CIN=8): GEMM role (fp32 W) + spmm role
// ---------------------------------------------------------------------------
template<int CIN, int COUT, bool FIRST, bool INIT, bool WITH_SPMM>
__global__ void __launch_bounds__(256) term_ffma_kernel(
    __half* __restrict__ Tnew, const __half* __restrict__ Tp1, const __half* __restrict__ Tp2,
    float* __restrict__ out, const float* __restrict__ W, const float* __restrict__ bias,
    const int* __restrict__ col, const float* __restrict__ vals)
{
    constexpr int NV = 4;
    constexpr int NG = V_NODES / NV;
    constexpr int OG = COUT / 16;
    constexpr int F8 = CIN * 2;
    constexpr int TPN = (F8 < 256) ? F8 : 256;
    constexpr int NPB = 256 / TPN;
    constexpr int SM_GEMM = NV * CIN * 16 + CIN * COUT;
    constexpr int SM_SPMM = 2 * NPB * DEG;
    constexpr int SM_SIZE = (SM_GEMM > SM_SPMM) ? SM_GEMM : SM_SPMM;
    __shared__ float smbuf[SM_SIZE];

    int tid = threadIdx.x;

    if (blockIdx.x < NG) {
        float* Ts = smbuf;
        float* Ws = smbuf + NV * CIN * 16;
        int b = tid & 15;
        int og = tid >> 4;
        int v0 = blockIdx.x * NV;

        // stage T (fp16 -> fp32) and W
        constexpr int TCNT = NV * CIN * 2;   // uint4s
        for (int i = tid; i < TCNT; i += 256) {
            int n = i / (CIN * 2);
            int r = i - n * (CIN * 2);
            uint4 raw = ((const uint4*)(Tp1 + (size_t)(v0 + n) * CIN * 16))[r];
            const __half2* h2 = (const __half2*)&raw;
            float* dst = Ts + n * CIN * 16 + r * 8;
#pragma unroll
            for (int j = 0; j < 4; j++) {
                float2 f = __half22float2(h2[j]);
                dst[2 * j] = f.x;
                dst[2 * j + 1] = f.y;
            }
        }
        for (int i = tid; i < CIN * COUT / 4; i += 256)
            ((float4*)Ws)[i] = ((const float4*)W)[i];
        __syncthreads();

        float acc[NV][OG];
#pragma unroll
        for (int j = 0; j < OG; j++) {
            float bv = INIT ? bias[og + 16 * j] : 0.f;
#pragma unroll
            for (int n = 0; n < NV; n++) acc[n][j] = bv;
        }
#pragma unroll
        for (int cc = 0; cc < CIN; cc++) {
            float tv[NV];
#pragma unroll
            for (int n = 0; n < NV; n++) tv[n] = Ts[n * CIN * 16 + cc * 16 + b];
#pragma unroll
            for (int j = 0; j < OG; j++) {
                float wv = Ws[cc * COUT + og + 16 * j];
#pragma unroll
                for (int n = 0; n < NV; n++) acc[n][j] = fmaf(tv[n], wv, acc[n][j]);
            }
        }
#pragma unroll
        for (int n = 0; n < NV; n++)
#pragma unroll
            for (int j = 0; j < OG; j++) {
                size_t idx = (size_t)(v0 + n) * COUT * 16 + (size_t)(og + 16 * j) * 16 + b;
                if (INIT) out[idx] = acc[n][j];
                else      out[idx] += acc[n][j];
            }
    } else if (WITH_SPMM) {
        spmm_role<CIN, FIRST>(blockIdx.x - NG, tid, smbuf, Tnew, Tp1, Tp2, col, vals);
    }
}

// ---------------------------------------------------------------------------
// BatchNorm stats (training mode) over (B,V) per channel, with relu-on-read.
// ---------------------------------------------------------------------------
__global__ void __launch_bounds__(256) bnstats_kernel(
    const float* __restrict__ h, const float* __restrict__ g,
    const float* __restrict__ be, float* __restrict__ ss, int C)
{
    int c = blockIdx.x;
    int F = C * 16;
    float s1 = 0.f, s2 = 0.f;
    for (int k = threadIdx.x; k < V_NODES * 16; k += 256) {
        int v = k >> 4, b = k & 15;
        float x = h[(size_t)v * F + c * 16 + b];
        x = fmaxf(x, 0.f);
        s1 += x;
        s2 += x * x;
    }
    __shared__ float r1[256], r2[256];
    r1[threadIdx.x] = s1; r2[threadIdx.x] = s2;
    __syncthreads();
    for (int s = 128; s > 0; s >>= 1) {
        if (threadIdx.x < s) {
            r1[threadIdx.x] += r1[threadIdx.x + s];
            r2[threadIdx.x] += r2[threadIdx.x + s];
        }
        __syncthreads();
    }
    if (threadIdx.x == 0) {
        float n = (float)(V_NODES * 16);
        float m = r1[0] / n;
        float var = r2[0] / n - m * m;
        float rstd = rsqrtf(var + 1e-5f);
        float sc = g[c] * rstd;
        ss[2 * c] = sc;
        ss[2 * c + 1] = be[c] - m * sc;
    }
}

// bn apply: fp32 in -> fp16 out (next layer's T0)
__global__ void __launch_bounds__(256) bnapply_kernel(
    __half2* __restrict__ out, const float4* __restrict__ in,
    const float* __restrict__ ss, int C, int n4)
{
    int i = blockIdx.x * 256 + threadIdx.x;
    if (i >= n4) return;
    int c = (i >> 2) % C;
    float sc = ss[2 * c], sh = ss[2 * c + 1];
    float4 v = in[i];
    v.x = fmaxf(v.x, 0.f) * sc + sh;
    v.y = fmaxf(v.y, 0.f) * sc + sh;
    v.z = fmaxf(v.z, 0.f) * sc + sh;
    v.w = fmaxf(v.w, 0.f) * sc + sh;
    out[2 * i]     = __floats2half2_rn(v.x, v.y);
    out[2 * i + 1] = __floats2half2_rn(v.z, v.w);
}

// ---------------------------------------------------------------------------
// Max-pool over V, stage 1
// ---------------------------------------------------------------------------
__global__ void pool1_kernel(float* __restrict__ pp, const float* __restrict__ h) {
    int col = blockIdx.x * 256 + threadIdx.x;
    int ch = blockIdx.y;
    int v0 = ch * 400;
    float m = -INFINITY;
    for (int v = v0; v < v0 + 400; v++) m = fmaxf(m, h[(size_t)v * 2048 + col]);
    pp[ch * 2048 + col] = m;
}

// ---------------------------------------------------------------------------
// Head: pool reduce + relu, BN over batch, linear 128->10, relu, log_softmax
// ---------------------------------------------------------------------------
__global__ void __launch_bounds__(256) head_kernel(
    float* __restrict__ out, const float* __restrict__ pp,
    const float* __restrict__ g, const float* __restrict__ be,
    const float* __restrict__ lw, const float* __restrict__ lb)
{
    __shared__ float pooled[2048];
    __shared__ float xbn[2048];
    __shared__ float logits[160];
    __shared__ float rowred[16];
    int t = threadIdx.x;

    for (int col = t; col < 2048; col += 256) {
        float m = -INFINITY;
        for (int ch = 0; ch < 25; ch++) m = fmaxf(m, pp[ch * 2048 + col]);
        pooled[col] = fmaxf(m, 0.f);
    }
    __syncthreads();

    if (t < 128) {
        float s1 = 0.f, s2 = 0.f;
        for (int b = 0; b < 16; b++) {
            float x = pooled[t * 16 + b];
            s1 += x; s2 += x * x;
        }
        float m = s1 / 16.f;
        float var = s2 / 16.f - m * m;
        float sc = g[t] * rsqrtf(var + 1e-5f);
        float sh = be[t] - m * sc;
        for (int b = 0; b < 16; b++) xbn[t * 16 + b] = pooled[t * 16 + b] * sc + sh;
    }
    __syncthreads();

    if (t < 160) {
        int b = t / 10, o = t % 10;
        float a = lb[o];
        for (int c = 0; c < 128; c++) a = fmaf(xbn[c * 16 + b], lw[c * 10 + o], a);
        logits[t] = fmaxf(a, 0.f);
    }
    __syncthreads();

    if (t < 16) {
        float m = -INFINITY;
        for (int o = 0; o < 10; o++) m = fmaxf(m, logits[t * 10 + o]);
        float s = 0.f;
        for (int o = 0; o < 10; o++) s += expf(logits[t * 10 + o] - m);
        rowred[t] = m + logf(s);
    }
    __syncthreads();

    if (t < 160) out[t] = logits[t] - rowred[t / 10];
}

// ---------------------------------------------------------------------------
// Host orchestration
// ---------------------------------------------------------------------------
extern "C" void kernel_launch(void* const* d_in, const int* in_sizes, int n_in,
                              void* d_out, int out_size) {
    const float* x      = (const float*)d_in[0];
    const float* w_in   = (const float*)d_in[1];
    const float* b_in   = (const float*)d_in[2];
    const float* g1     = (const float*)d_in[3];
    const float* be1    = (const float*)d_in[4];
    const float* w1a    = (const float*)d_in[5];
    const float* b1a    = (const float*)d_in[6];
    const float* g1h    = (const float*)d_in[7];
    const float* be1h   = (const float*)d_in[8];
    const float* w1b    = (const float*)d_in[9];
    const float* b1b    = (const float*)d_in[10];
    const float* sc1    = (const float*)d_in[11];
    const float* g2     = (const float*)d_in[12];
    const float* be2    = (const float*)d_in[13];
    const float* w2a    = (const float*)d_in[14];
    const float* b2a    = (const float*)d_in[15];
    const float* g2h    = (const float*)d_in[16];
    const float* be2h   = (const float*)d_in[17];
    const float* w2b    = (const float*)d_in[18];
    const float* b2b    = (const float*)d_in[19];
    const float* sc2    = (const float*)d_in[20];
    const float* g_out  = (const float*)d_in[21];
    const float* be_out = (const float*)d_in[22];
    const float* lin_w  = (const float*)d_in[23];
    const float* lin_b  = (const float*)d_in[24];
    const float* vals   = (const float*)d_in[25];
    const int*   lidx   = (const int*)d_in[26];
    const int*   col    = lidx + E_EDGES;

    float* base = nullptr;
    cudaGetSymbolAddress((void**)&base, g_buf);
    __half* H0 = (__half*)(base + 0 * BUFSZ);
    __half* H1 = (__half*)(base + 1 * BUFSZ);
    __half* H2 = (__half*)(base + 2 * BUFSZ);
    __half* H3 = (__half*)(base + 3 * BUFSZ);
    float*  B4 = base + 4 * BUFSZ;
    float*  B5 = base + 5 * BUFSZ;
    __half* H5 = (__half*)(base + 3 * BUFSZ + BUFSZ / 2);
    float* st0 = base + 6 * BUFSZ;
    float* st1 = st0 + 256;
    float* st2 = st1 + 256;
    float* st3 = st2 + 256;
    float* pp  = st3 + 256;
    float* scr = pp + 25 * 2048;

    // fp16 weight splits (offsets in halves; all multiples of 2048)
    __half* hscr = (__half*)scr;
    __half* w1a_hi = hscr + 0;       __half* w1a_lo = hscr + 12288;
    __half* w1b_hi = hscr + 24576;   __half* w1b_lo = hscr + 49152;
    __half* sc1_hi = hscr + 73728;   __half* sc1_lo = hscr + 75776;
    __half* w2a_hi = hscr + 77824;   __half* w2a_lo = hscr + 126976;
    __half* w2b_hi = hscr + 176128;  __half* w2b_lo = hscr + 274432;
    __half* sc2_hi = hscr + 372736;  __half* sc2_lo = hscr + 380928;
    float* bt1a = scr + 194560;      // 16*64
    float* bt1b = bt1a + 1024;       // 16*64
    float* bt2a = bt1b + 1024;       // 16*128
    float* bt2b = bt2a + 2048;       // 16*128

    // one-time conversions (cheap, deterministic)
    wsplit_kernel<<<(12288 + 255) / 256, 256>>>(w1a_hi, w1a_lo, w1a, 12288);
    wsplit_kernel<<<(24576 + 255) / 256, 256>>>(w1b_hi, w1b_lo, w1b, 24576);
    wsplit_kernel<<<(2048  + 255) / 256, 256>>>(sc1_hi, sc1_lo, sc1, 2048);
    wsplit_kernel<<<(49152 + 255) / 256, 256>>>(w2a_hi, w2a_lo, w2a, 49152);
    wsplit_kernel<<<(98304 + 255) / 256, 256>>>(w2b_hi, w2b_lo, w2b, 98304);
    wsplit_kernel<<<(8192  + 255) / 256, 256>>>(sc2_hi, sc2_lo, sc2, 8192);
    btile_kernel<<<4, 256>>>(bt1a, b1a, 64);
    btile_kernel<<<4, 256>>>(bt1b, b1b, 64);
    btile_kernel<<<8, 256>>>(bt2a, b2a, 128);
    btile_kernel<<<8, 256>>>(bt2b, b2b, 128);

    const int NG = V_NODES / 4;

    // ===== Layer 1: cheb(x, w_in, b_in), Cin=8 Cout=32 (FFMA path), out=B4 =====
    transpose_x_kernel<<<(V_NODES * 128 + 255) / 256, 256>>>(H0, x);
    {
        const int NS = ns_for(8), G = NG + NS;
        term_ffma_kernel<8, 32, true,  true,  true ><<<G, 256>>>(H1, H0, nullptr, B4, w_in,           b_in,   col, vals);
        term_ffma_kernel<8, 32, false, false, true ><<<G, 256>>>(H2, H1, H0,      B4, w_in + 1 * 256, nullptr, col, vals);
        term_ffma_kernel<8, 32, false, false, true ><<<G, 256>>>(H0, H2, H1,      B4, w_in + 2 * 256, nullptr, col, vals);
        term_ffma_kernel<8, 32, false, false, true ><<<G, 256>>>(H1, H0, H2,      B4, w_in + 3 * 256, nullptr, col, vals);
        term_ffma_kernel<8, 32, false, false, true ><<<G, 256>>>(H2, H1, H0,      B4, w_in + 4 * 256, nullptr, col, vals);
        term_ffma_kernel<8, 32, false, false, false><<<NG, 256>>>(nullptr, H2, nullptr, B4, w_in + 5 * 256, nullptr, col, vals);
    }

    // ===== Block 1 =====
    bnstats_kernel<<<32, 256>>>(B4, g1, be1, st0, 32);
    bnapply_kernel<<<(V_NODES * 32 * 4 + 255) / 256, 256>>>((__half2*)H3, (const float4*)B4, st0, 32, V_NODES * 32 * 4);
    // chebA: 32 -> 64 (mma), in=H3 kept, out=B5; NGEMM = V/2 = 5000
    {
        const int NGE = V_NODES / 2, NS = ns_for(32);
        term_mma_kernel<32, 64, 0, true,  true,  true ><<<NGE + NS, 256>>>(H1, H3, nullptr, B5, w1a_hi,             w1a_lo,             bt1a, nullptr, nullptr, nullptr, col, vals);
        term_mma_kernel<32, 64, 0, false, false, true ><<<NGE + NS, 256>>>(H2, H1, H3,      B5, w1a_hi + 1 * 2048,  w1a_lo + 1 * 2048,  bt1a, nullptr, nullptr, nullptr, col, vals);
        term_mma_kernel<32, 64, 0, false, false, true ><<<NGE + NS, 256>>>(H0, H2, H1,      B5, w1a_hi + 2 * 2048,  w1a_lo + 2 * 2048,  bt1a, nullptr, nullptr, nullptr, col, vals);
        term_mma_kernel<32, 64, 0, false, false, true ><<<NGE + NS, 256>>>(H1, H0, H2,      B5, w1a_hi + 3 * 2048,  w1a_lo + 3 * 2048,  bt1a, nullptr, nullptr, nullptr, col, vals);
        term_mma_kernel<32, 64, 0, false, false, true ><<<NGE + NS, 256>>>(H2, H1, H0,      B5, w1a_hi + 4 * 2048,  w1a_lo + 4 * 2048,  bt1a, nullptr, nullptr, nullptr, col, vals);
        term_mma_kernel<32, 64, 0, false, false, false><<<NGE, 256>>>(nullptr, H2, nullptr, B5, w1a_hi + 5 * 2048,  w1a_lo + 5 * 2048,  bt1a, nullptr, nullptr, nullptr, col, vals);
    }
    bnstats_kernel<<<64, 256>>>(B5, g1h, be1h, st1, 64);
    bnapply_kernel<<<(V_NODES * 64 * 4 + 255) / 256, 256>>>((__half2*)H0, (const float4*)B5, st1, 64, V_NODES * 64 * 4);
    // chebB: 64 -> 64 (mma, + shortcut H3@sc1 in k=0), in=H0, out=B4; NGEMM = 5000
    {
        const int NGE = V_NODES / 2, NS = ns_for(64);
        term_mma_kernel<64, 64, 32, true,  true,  true ><<<NGE + NS, 256>>>(H1, H0, nullptr, B4, w1b_hi,            w1b_lo,            bt1b, H3, sc1_hi, sc1_lo, col, vals);
        term_mma_kernel<64, 64, 0,  false, false, true ><<<NGE + NS, 256>>>(H2, H1, H0,      B4, w1b_hi + 1 * 4096, w1b_lo + 1 * 4096, bt1b, nullptr, nullptr, nullptr, col, vals);
        term_mma_kernel<64, 64, 0,  false, false, true ><<<NGE + NS, 256>>>(H5, H2, H1,      B4, w1b_hi + 2 * 4096, w1b_lo + 2 * 4096, bt1b, nullptr, nullptr, nullptr, col, vals);
        term_mma_kernel<64, 64, 0,  false, false, true ><<<NGE + NS, 256>>>(H1, H5, H2,      B4, w1b_hi + 3 * 4096, w1b_lo + 3 * 4096, bt1b, nullptr, nullptr, nullptr, col, vals);
        term_mma_kernel<64, 64, 0,  false, false, true ><<<NGE + NS, 256>>>(H2, H1, H5,      B4, w1b_hi + 4 * 4096, w1b_lo + 4 * 4096, bt1b, nullptr, nullptr, nullptr, col, vals);
        term_mma_kernel<64, 64, 0,  false, false, false><<<NGE, 256>>>(nullptr, H2, nullptr, B4, w1b_hi + 5 * 4096, w1b_lo + 5 * 4096, bt1b, nullptr, nullptr, nullptr, col, vals);
    }

    // ===== Block 2 =====
    bnstats_kernel<<<64, 256>>>(B4, g2, be2, st2, 64);
    bnapply_kernel<<<(V_NODES * 64 * 4 + 255) / 256, 256>>>((__half2*)H3, (const float4*)B4, st2, 64, V_NODES * 64 * 4);
    // chebA: 64 -> 128 (mma), in=H3 kept, out=B5; NGEMM = 10000
    {
        const int NGE = V_NODES, NS = ns_for(64);
        term_mma_kernel<64, 128, 0, true,  true,  true ><<<NGE + NS, 256>>>(H1, H3, nullptr, B5, w2a_hi,            w2a_lo,            bt2a, nullptr, nullptr, nullptr, col, vals);
        term_mma_kernel<64, 128, 0, false, false, true ><<<NGE + NS, 256>>>(H2, H1, H3,      B5, w2a_hi + 1 * 8192, w2a_lo + 1 * 8192, bt2a, nullptr, nullptr, nullptr, col, vals);
        term_mma_kernel<64, 128, 0, false, false, true ><<<NGE + NS, 256>>>(H0, H2, H1,      B5, w2a_hi + 2 * 8192, w2a_lo + 2 * 8192, bt2a, nullptr, nullptr, nullptr, col, vals);
        term_mma_kernel<64, 128, 0, false, false, true ><<<NGE + NS, 256>>>(H1, H0, H2,      B5, w2a_hi + 3 * 8192, w2a_lo + 3 * 8192, bt2a, nullptr, nullptr, nullptr, col, vals);
        term_mma_kernel<64, 128, 0, false, false, true ><<<NGE + NS, 256>>>(H2, H1, H0,      B5, w2a_hi + 4 * 8192, w2a_lo + 4 * 8192, bt2a, nullptr, nullptr, nullptr, col, vals);
        term_mma_kernel<64, 128, 0, false, false, false><<<NGE, 256>>>(nullptr, H2, nullptr, B5, w2a_hi + 5 * 8192, w2a_lo + 5 * 8192, bt2a, nullptr, nullptr, nullptr, col, vals);
    }
    bnstats_kernel<<<128, 256>>>(B5, g2h, be2h, st3, 128);
    bnapply_kernel<<<(V_NODES * 128 * 4 + 255) / 256, 256>>>((__half2*)H0, (const float4*)B5, st3, 128, V_NODES * 128 * 4);
    // chebB: 128 -> 128 (mma, + shortcut H3@sc2 in k=0), in=H0, out=B4; NGEMM = 10000
    {
        const int NGE = V_NODES, NS = ns_for(128);
        term_mma_kernel<128, 128, 64, true,  true,  true ><<<NGE + NS, 256>>>(H1, H0, nullptr, B4, w2b_hi,             w2b_lo,             bt2b, H3, sc2_hi, sc2_lo, col, vals);
        term_mma_kernel<128, 128, 0,  false, false, true ><<<NGE + NS, 256>>>(H2, H1, H0,      B4, w2b_hi + 1 * 16384, w2b_lo + 1 * 16384, bt2b, nullptr, nullptr, nullptr, col, vals);
        term_mma_kernel<128, 128, 0,  false, false, true ><<<NGE + NS, 256>>>(H5, H2, H1,      B4, w2b_hi + 2 * 16384, w2b_lo + 2 * 16384, bt2b, nullptr, nullptr, nullptr, col, vals);
        term_mma_kernel<128, 128, 0,  false, false, true ><<<NGE + NS, 256>>>(H1, H5, H2,      B4, w2b_hi + 3 * 16384, w2b_lo + 3 * 16384, bt2b, nullptr, nullptr, nullptr, col, vals);
        term_mma_kernel<128, 128, 0,  false, false, true ><<<NGE + NS, 256>>>(H2, H1, H5,      B4, w2b_hi + 4 * 16384, w2b_lo + 4 * 16384, bt2b, nullptr, nullptr, nullptr, col, vals);
        term_mma_kernel<128, 128, 0,  false, false, false><<<NGE, 256>>>(nullptr, H2, nullptr, B4, w2b_hi + 5 * 16384, w2b_lo + 5 * 16384, bt2b, nullptr, nullptr, nullptr, col, vals);
    }

    // ===== Head =====
    pool1_kernel<<<dim3(8, 25), 256>>>(pp, B4);
    head_kernel<<<1, 256>>>((float*)d_out, pp, g_out, be_out, lin_w, lin_b);
}